// round 3
// baseline (speedup 1.0000x reference)
#include <cuda_runtime.h>
#include <math.h>

// GaussianVoxelizer: grid 100x100x8 = 80000 voxels, 128 gaussians, 16 features.
// Voxel centers are analytic: coord = (i + 0.5)*0.8 + lo, lo = (-40,-40,-1).
#define NVOX 80000
#define NG   128
#define NF   16
#define TPB  800          // 25 warps; one 10x10x8 tile (800 voxels), 1 vox/thread
#define NBLK 100          // 10 x-tiles * 10 y-tiles; single wave on 148 SMs

// Packed per-gaussian fields (stride NG):
// 0..2 mean xyz | 3..5 inv00,inv11,inv22 | 6..8 2*inv01,2*inv02,2*inv12 | 9 opacity
#define PF 10

__global__ __launch_bounds__(TPB) void gv_kernel(const float* __restrict__ means,
                                                 const float* __restrict__ opac,
                                                 const float* __restrict__ feats,
                                                 const float* __restrict__ covs,
                                                 float* __restrict__ out) {
    __shared__ float s_feat[NG * NF];   // 8 KB raw features [g][k]
    __shared__ float sp[PF * NG];       // 5 KB packed params
    __shared__ int   s_list[NG];        // per-warp segments: warp w -> [w*32, w*32+cnt)
    __shared__ int   s_wcnt[4];

    int tid = threadIdx.x;

    // Tile coords: block = (xt, yt) 10x10 xy tile, full z.
    int xt = blockIdx.x / 10;
    int yt = blockIdx.x - xt * 10;
    int lx  = tid / 80;
    int rem = tid - lx * 80;
    int ly  = rem >> 3;
    int lz  = rem & 7;
    int x = xt * 10 + lx;
    int y = yt * 10 + ly;
    // Analytic voxel center (same fp32 ops as reference grid generation).
    float px = ((float)x + 0.5f) * 0.8f + (-40.0f);
    float py = ((float)y + 0.5f) * 0.8f + (-40.0f);
    float pz = ((float)lz + 0.5f) * 0.8f + (-1.0f);

    // Stage features cooperatively (2048 floats / 800 threads -> 3 iters).
    for (int i = tid; i < NG * NF; i += TPB) s_feat[i] = feats[i];

    // Tile AABB over voxel centers.
    float bxmin = ((float)(xt * 10) + 0.5f) * 0.8f - 40.0f;
    float bxmax = ((float)(xt * 10) + 9.5f) * 0.8f - 40.0f;
    float bymin = ((float)(yt * 10) + 0.5f) * 0.8f - 40.0f;
    float bymax = ((float)(yt * 10) + 9.5f) * 0.8f - 40.0f;
    float bzmin = 0.5f * 0.8f - 1.0f;
    float bzmax = 7.5f * 0.8f - 1.0f;

    // Warps 0..3: prep gaussian g = tid (inverse, pack) + cull, fused, register bbox.
    if (tid < NG) {
        int g = tid;
        float a = covs[g * 9 + 0], b = covs[g * 9 + 1], c = covs[g * 9 + 2];
        float d = covs[g * 9 + 4], e = covs[g * 9 + 5], f = covs[g * 9 + 8];
        float c00 = d * f - e * e;
        float c01 = c * e - b * f;
        float c02 = b * e - c * d;
        float det = a * c00 + b * c01 + c * c02;
        float id  = 1.0f / det;

        float mx = means[g * 3 + 0];
        float my = means[g * 3 + 1];
        float mz = means[g * 3 + 2];

        sp[0 * NG + g] = mx;
        sp[1 * NG + g] = my;
        sp[2 * NG + g] = mz;
        sp[3 * NG + g] = c00 * id;
        sp[4 * NG + g] = (a * f - c * c) * id;
        sp[5 * NG + g] = (a * d - b * b) * id;
        sp[6 * NG + g] = 2.0f * c01 * id;
        sp[7 * NG + g] = 2.0f * c02 * id;
        sp[8 * NG + g] = 2.0f * (b * c - a * e) * id;
        sp[9 * NG + g] = opac[g];

        // Conservative AABB of maha<=4 ellipsoid: mu +- 2*sqrt(C_kk) (+margin).
        const float margin = 1e-3f;
        float ex = 2.0f * sqrtf(fmaxf(a, 0.0f)) + margin;
        float ey = 2.0f * sqrtf(fmaxf(d, 0.0f)) + margin;
        float ez = 2.0f * sqrtf(fmaxf(f, 0.0f)) + margin;

        bool keep = (mx - ex <= bxmax) & (mx + ex >= bxmin) &
                    (my - ey <= bymax) & (my + ey >= bymin) &
                    (mz - ez <= bzmax) & (mz + ez >= bzmin);
        unsigned m = __ballot_sync(0xffffffffu, keep);
        int lane = g & 31;
        int warp = g >> 5;
        if (keep) s_list[warp * 32 + __popc(m & ((1u << lane) - 1u))] = g;
        if (lane == 0) s_wcnt[warp] = __popc(m);
    }
    __syncthreads();   // the only block-wide barrier

    float cnt = 0.0f, sumd = 0.0f;
    float sumf[NF];
#pragma unroll
    for (int k = 0; k < NF; k++) sumf[k] = 0.0f;

#pragma unroll
    for (int w = 0; w < 4; w++) {
        int c = s_wcnt[w];
        for (int s = 0; s < c; s++) {
            int g = s_list[w * 32 + s];           // uniform per warp -> LDS broadcast
            float dx = px - sp[0 * NG + g];
            float dy = py - sp[1 * NG + g];
            float dz = pz - sp[2 * NG + g];
            float maha = sp[3 * NG + g] * dx * dx;
            maha = fmaf(sp[4 * NG + g], dy * dy, maha);
            maha = fmaf(sp[5 * NG + g], dz * dz, maha);
            maha = fmaf(sp[6 * NG + g], dx * dy, maha);
            maha = fmaf(sp[7 * NG + g], dx * dz, maha);
            maha = fmaf(sp[8 * NG + g], dy * dz, maha);
            if (maha <= 4.0f) {
                float wgt   = __expf(-0.5f * maha);
                float scale = sp[9 * NG + g] * wgt;   // opac * w
                cnt  += 1.0f;
                sumd += scale;
                const float* fg = s_feat + g * NF;    // uniform -> broadcast
#pragma unroll
                for (int k = 0; k < NF; k++)
                    sumf[k] = fmaf(scale, fg[k], sumf[k]);
            }
        }
    }

    int n = (x * 100 + y) * 8 + lz;
    float inv = (cnt > 0.0f) ? (1.0f / cnt) : 0.0f;
    out[n] = sumd * inv;
    float4* fo = reinterpret_cast<float4*>(out + NVOX + (size_t)n * NF);
    fo[0] = make_float4(sumf[0] * inv,  sumf[1] * inv,  sumf[2] * inv,  sumf[3] * inv);
    fo[1] = make_float4(sumf[4] * inv,  sumf[5] * inv,  sumf[6] * inv,  sumf[7] * inv);
    fo[2] = make_float4(sumf[8] * inv,  sumf[9] * inv,  sumf[10] * inv, sumf[11] * inv);
    fo[3] = make_float4(sumf[12] * inv, sumf[13] * inv, sumf[14] * inv, sumf[15] * inv);
}

extern "C" void kernel_launch(void* const* d_in, const int* in_sizes, int n_in,
                              void* d_out, int out_size) {
    // d_in[0] = grid_coords (unused: analytic), [1]=means, [2]=opac, [3]=feats, [4]=covs
    const float* means = (const float*)d_in[1];
    const float* opac  = (const float*)d_in[2];
    const float* feats = (const float*)d_in[3];
    const float* covs  = (const float*)d_in[4];
    float* out = (float*)d_out;

    gv_kernel<<<NBLK, TPB>>>(means, opac, feats, covs, out);
}

// round 5
// speedup vs baseline: 1.1801x; 1.1801x over previous
#include <cuda_runtime.h>
#include <math.h>

// GaussianVoxelizer: 100x100x8 voxels, 128 gaussians, 16 features.
// Voxel centers analytic: coord = (i + 0.5f)*0.8f + lo, lo = (-40,-40,-1).
#define NVOX 80000
#define NG   128
#define NF   16
#define TPB  128
// Tile: 4 (x) * 8 (y) * 8 (z) = 256 voxels; thread handles z-pair {2t, 2t+1}.
// Grid: 25 x-tiles * 13 y-tiles = 325 blocks (y predicated at 100).
#define NXT  25
#define NYT  13

__global__ __launch_bounds__(TPB) void gv_kernel(const float* __restrict__ means,
                                                 const float* __restrict__ opac,
                                                 const float* __restrict__ feats,
                                                 const float* __restrict__ covs,
                                                 float* __restrict__ out) {
    __shared__ float4 s_v0[NG];          // {mx, my, mz, opac}
    __shared__ float4 s_v1[NG];          // {i00, i11, 2*i01, i22}
    __shared__ float2 s_v2[NG];          // {2*i02, 2*i12}
    __shared__ float4 s_feat[NG * 4];    // features as 4x float4 per gaussian
    __shared__ int    s_list[NG];        // per-warp segments [w*32, w*32+cnt)
    __shared__ int    s_wcnt[4];

    int tid = threadIdx.x;
    int xt  = blockIdx.x / NYT;
    int yt  = blockIdx.x - xt * NYT;

    int lx  = tid >> 5;            // 0..3
    int ly  = (tid >> 2) & 7;      // 0..7
    int lzp = tid & 3;             // z-pair index -> z0 = 2*lzp
    int x   = xt * 4 + lx;         // < 100 always
    int y   = yt * 8 + ly;         // may reach 103
    int z0  = lzp * 2;

    float px  = ((float)x  + 0.5f) * 0.8f + (-40.0f);
    float py  = ((float)y  + 0.5f) * 0.8f + (-40.0f);
    float pz0 = ((float)z0 + 0.5f) * 0.8f + (-1.0f);
    float pz1 = ((float)(z0 + 1) + 0.5f) * 0.8f + (-1.0f);

    // Stage features as float4 (512 vecs / 128 threads = 4 iters).
    const float4* f4 = (const float4*)feats;
#pragma unroll
    for (int i = tid; i < NG * 4; i += TPB) s_feat[i] = f4[i];

    // Tile AABB over in-range voxel centers.
    float bxmin = ((float)(xt * 4) + 0.5f) * 0.8f - 40.0f;
    float bxmax = ((float)(xt * 4) + 3.5f) * 0.8f - 40.0f;
    int   ymaxc = min(yt * 8 + 7, 99);
    float bymin = ((float)(yt * 8) + 0.5f) * 0.8f - 40.0f;
    float bymax = ((float)ymaxc + 0.5f) * 0.8f - 40.0f;
    const float bzmin = 0.5f * 0.8f - 1.0f;
    const float bzmax = 7.5f * 0.8f - 1.0f;

    // All 128 threads: prep gaussian tid (inverse, pack) + cull.
    {
        int g = tid;
        float a = covs[g * 9 + 0], b = covs[g * 9 + 1], c = covs[g * 9 + 2];
        float d = covs[g * 9 + 4], e = covs[g * 9 + 5], f = covs[g * 9 + 8];
        float c00 = d * f - e * e;
        float c01 = c * e - b * f;
        float c02 = b * e - c * d;
        float det = a * c00 + b * c01 + c * c02;
        float id  = 1.0f / det;

        float mx = means[g * 3 + 0];
        float my = means[g * 3 + 1];
        float mz = means[g * 3 + 2];

        s_v0[g] = make_float4(mx, my, mz, opac[g]);
        s_v1[g] = make_float4(c00 * id, (a * f - c * c) * id,
                              2.0f * c01 * id, (a * d - b * b) * id);
        s_v2[g] = make_float2(2.0f * c02 * id, 2.0f * (b * c - a * e) * id);

        // Conservative AABB of maha<=4: mu +- 2*sqrt(C_kk) (+margin).
        const float margin = 1e-3f;
        float ex = 2.0f * sqrtf(fmaxf(a, 0.0f)) + margin;
        float ey = 2.0f * sqrtf(fmaxf(d, 0.0f)) + margin;
        float ez = 2.0f * sqrtf(fmaxf(f, 0.0f)) + margin;

        bool keep = (mx - ex <= bxmax) & (mx + ex >= bxmin) &
                    (my - ey <= bymax) & (my + ey >= bymin) &
                    (mz - ez <= bzmax) & (mz + ez >= bzmin);
        unsigned m = __ballot_sync(0xffffffffu, keep);
        int lane = g & 31;
        int warp = g >> 5;
        if (keep) s_list[warp * 32 + __popc(m & ((1u << lane) - 1u))] = g;
        if (lane == 0) s_wcnt[warp] = __popc(m);
    }
    __syncthreads();   // only barrier

    float cnt0 = 0.0f, cnt1 = 0.0f, sumd0 = 0.0f, sumd1 = 0.0f;
    float sf0[NF], sf1[NF];
#pragma unroll
    for (int k = 0; k < NF; k++) { sf0[k] = 0.0f; sf1[k] = 0.0f; }

#pragma unroll
    for (int w = 0; w < 4; w++) {
        int c = s_wcnt[w];
        for (int s = 0; s < c; s++) {
            int g = s_list[w * 32 + s];          // uniform -> LDS broadcast
            float4 v0 = s_v0[g];
            float4 v1 = s_v1[g];
            float2 v2 = s_v2[g];
            float dx = px - v0.x;
            float dy = py - v0.y;
            float dz0 = pz0 - v0.z;
            float dz1 = pz1 - v0.z;
            // A = i00*dx^2 + i11*dy^2 + 2i01*dx*dy ; B = 2i02*dx + 2i12*dy
            float A = fmaf(v1.x, dx * dx, fmaf(v1.y, dy * dy, v1.z * (dx * dy)));
            float B = fmaf(v2.x, dx, v2.y * dy);
            float m0 = fmaf(dz0, fmaf(v1.w, dz0, B), A);
            float m1 = fmaf(dz1, fmaf(v1.w, dz1, B), A);
            // Branchless: w=0 outside mask contributes nothing.
            float w0 = (m0 <= 4.0f) ? __expf(-0.5f * m0) : 0.0f;
            float w1 = (m1 <= 4.0f) ? __expf(-0.5f * m1) : 0.0f;
            cnt0 += (m0 <= 4.0f) ? 1.0f : 0.0f;
            cnt1 += (m1 <= 4.0f) ? 1.0f : 0.0f;
            float s0 = v0.w * w0;
            float s1 = v0.w * w1;
            sumd0 += s0;
            sumd1 += s1;
            const float4* fg = s_feat + g * 4;   // uniform -> broadcast
#pragma unroll
            for (int j = 0; j < 4; j++) {
                float4 fv = fg[j];
                sf0[j * 4 + 0] = fmaf(s0, fv.x, sf0[j * 4 + 0]);
                sf0[j * 4 + 1] = fmaf(s0, fv.y, sf0[j * 4 + 1]);
                sf0[j * 4 + 2] = fmaf(s0, fv.z, sf0[j * 4 + 2]);
                sf0[j * 4 + 3] = fmaf(s0, fv.w, sf0[j * 4 + 3]);
                sf1[j * 4 + 0] = fmaf(s1, fv.x, sf1[j * 4 + 0]);
                sf1[j * 4 + 1] = fmaf(s1, fv.y, sf1[j * 4 + 1]);
                sf1[j * 4 + 2] = fmaf(s1, fv.z, sf1[j * 4 + 2]);
                sf1[j * 4 + 3] = fmaf(s1, fv.w, sf1[j * 4 + 3]);
            }
        }
    }

    if (y < 100) {
        int n0 = (x * 100 + y) * 8 + z0;
        float inv0 = (cnt0 > 0.0f) ? (1.0f / cnt0) : 0.0f;
        float inv1 = (cnt1 > 0.0f) ? (1.0f / cnt1) : 0.0f;
        out[n0]     = sumd0 * inv0;
        out[n0 + 1] = sumd1 * inv1;
        float4* fo0 = (float4*)(out + NVOX + (size_t)n0 * NF);
        float4* fo1 = fo0 + 4;
#pragma unroll
        for (int j = 0; j < 4; j++) {
            fo0[j] = make_float4(sf0[j*4+0]*inv0, sf0[j*4+1]*inv0,
                                 sf0[j*4+2]*inv0, sf0[j*4+3]*inv0);
            fo1[j] = make_float4(sf1[j*4+0]*inv1, sf1[j*4+1]*inv1,
                                 sf1[j*4+2]*inv1, sf1[j*4+3]*inv1);
        }
    }
}

extern "C" void kernel_launch(void* const* d_in, const int* in_sizes, int n_in,
                              void* d_out, int out_size) {
    // d_in[0] = grid_coords (unused: analytic), [1]=means, [2]=opac, [3]=feats, [4]=covs
    const float* means = (const float*)d_in[1];
    const float* opac  = (const float*)d_in[2];
    const float* feats = (const float*)d_in[3];
    const float* covs  = (const float*)d_in[4];
    float* out = (float*)d_out;

    gv_kernel<<<NXT * NYT, TPB>>>(means, opac, feats, covs, out);
}